// round 3
// baseline (speedup 1.0000x reference)
#include <cuda_runtime.h>
#include <cuda_fp16.h>
#include <mma.h>

using namespace nvcuda;

#define S 4096
#define D 128
#define H 128
#define BATCH 2
#define KDIM 256   // concatenated [real|imag] inner dim

// ----------------------------- scratch (device globals: allocation-free) ---
__device__ float  g_Weff[4][KDIM][KDIM];       // packed effective weights (q,k,v,p)
__device__ float  g_beff[4][KDIM];
__device__ float  g_QKVf[BATCH*3][S][KDIM];    // fp32 projections, z = b*3 + {q,k,v}
__device__ __half g_Q16[BATCH][S][KDIM];
__device__ __half g_K16[BATCH][S][KDIM];
__device__ __half g_V16[BATCH][S][KDIM];
__device__ float  g_q2[BATCH][S];
__device__ float  g_k2[BATCH][S];
__device__ float  g_cumV[BATCH][S][KDIM];      // inclusive prefix sum of V over t
__device__ __half g_P16[BATCH][S][S];          // (w - 1/(s+1)) * 1024, fp16
__device__ float  g_est[BATCH][S][KDIM];

// --------------------------------------------------------------------------
// Pack Weff / beff for one projection p:
//  out_r(j<128):  k<128 -> Wr[j][k],    k>=128 -> -Wi[j][k-128];  bias br-bi
//  out_i(j>=128): k<128 -> Wi[m][k],    k>=128 ->  Wr[m][k-128];  bias br+bi
__global__ void pack_weights_kernel(int p, const float* __restrict__ Wr,
                                    const float* __restrict__ Wi,
                                    const float* __restrict__ br,
                                    const float* __restrict__ bi) {
    int k = blockIdx.x;       // 0..255
    int j = threadIdx.x;      // 0..255
    float w;
    if (j < 128) {
        w = (k < 128) ? Wr[j * D + k] : -Wi[j * D + (k - 128)];
    } else {
        int m = j - 128;
        w = (k < 128) ? Wi[m * D + k] : Wr[m * D + (k - 128)];
    }
    g_Weff[p][k][j] = w;
    if (k == 0) {
        g_beff[p][j] = (j < 128) ? (br[j] - bi[j]) : (br[j - 128] + bi[j - 128]);
    }
}

// --------------------------------------------------------------------------
// fp32 SIMT GEMM: C[128x128 tile] = A[., 256] x W[256, 256] + bias
// zmode=1: A(s,k) read from Z batch base: plane (k>>7), element (k&127)
// outMode=0: contiguous [S][KDIM]; outMode=1: complex-out mapping into d_out
__device__ __forceinline__ void gemm128_body(const float* __restrict__ Abase, int zmode,
                                             const float* __restrict__ W,
                                             const float* __restrict__ bias,
                                             float* __restrict__ Cout, int outMode, int b) {
    int s0 = blockIdx.y * 128;
    int j0 = blockIdx.x * 128;
    __shared__ float As[8][128];
    __shared__ float Bs[8][128];
    int tid = threadIdx.x;
    int tx = tid & 15, ty = tid >> 4;
    int m0 = ty * 8, n0 = tx * 8;
    float acc[8][8];
#pragma unroll
    for (int i = 0; i < 8; i++)
#pragma unroll
        for (int j = 0; j < 8; j++) acc[i][j] = 0.f;

    int ar  = tid >> 1;          // 0..127
    int ak  = (tid & 1) * 4;     // 0 or 4
    int brw = tid >> 5;          // 0..7
    int bc  = (tid & 31) * 4;    // 0..124

    for (int kc = 0; kc < KDIM; kc += 8) {
        float4 av;
        int kk = kc + ak;
        if (zmode) {
            av = *(const float4*)(Abase + (size_t)(kk >> 7) * (S * D)
                                        + (size_t)(s0 + ar) * D + (kk & 127));
        } else {
            av = *(const float4*)(Abase + (size_t)(s0 + ar) * KDIM + kk);
        }
        As[ak + 0][ar] = av.x; As[ak + 1][ar] = av.y;
        As[ak + 2][ar] = av.z; As[ak + 3][ar] = av.w;
        *(float4*)&Bs[brw][bc] = *(const float4*)(W + (size_t)(kc + brw) * KDIM + j0 + bc);
        __syncthreads();
#pragma unroll
        for (int k = 0; k < 8; k++) {
            float a[8], bb[8];
            *(float4*)a        = *(float4*)&As[k][m0];
            *(float4*)(a + 4)  = *(float4*)&As[k][m0 + 4];
            *(float4*)bb       = *(float4*)&Bs[k][n0];
            *(float4*)(bb + 4) = *(float4*)&Bs[k][n0 + 4];
#pragma unroll
            for (int i = 0; i < 8; i++)
#pragma unroll
                for (int j = 0; j < 8; j++)
                    acc[i][j] = fmaf(a[i], bb[j], acc[i][j]);
        }
        __syncthreads();
    }

#pragma unroll
    for (int i = 0; i < 8; i++) {
        int s = s0 + m0 + i;
#pragma unroll
        for (int j = 0; j < 8; j++) {
            int jj = j0 + n0 + j;
            float v = acc[i][j] + bias[jj];
            if (outMode == 0) {
                Cout[(size_t)s * KDIM + jj] = v;
            } else {
                int c = jj >> 7, h = jj & 127;
                Cout[((size_t)(b * 2 + c) * S + s) * H + h] = v;
            }
        }
    }
}

__global__ __launch_bounds__(256) void proj_kernel(const float* __restrict__ Zq,
                                                   const float* __restrict__ Zk,
                                                   const float* __restrict__ Zv) {
    int z = blockIdx.z;
    int b = z / 3, p = z % 3;
    const float* Zb = ((p == 0) ? Zq : (p == 1) ? Zk : Zv) + (size_t)b * 2 * S * D;
    gemm128_body(Zb, 1, &g_Weff[p][0][0], &g_beff[p][0], &g_QKVf[z][0][0], 0, b);
}

__global__ __launch_bounds__(256) void outproj_kernel(float* __restrict__ out) {
    int b = blockIdx.z;
    gemm128_body(&g_est[b][0][0], 0, &g_Weff[3][0][0], &g_beff[3][0], out, 1, b);
}

// --------------------------------------------------------------------------
// fp16 copies + q2/k2 row sums (from fp32 projections)
__global__ __launch_bounds__(256) void convert_kernel() {
    int s  = blockIdx.x;
    int bp = blockIdx.y;
    int b = bp / 3, p = bp % 3;
    int tid = threadIdx.x;
    float v = g_QKVf[bp][s][tid];
    __half h = __float2half(v);
    if (p == 0)      g_Q16[b][s][tid] = h;
    else if (p == 1) g_K16[b][s][tid] = h;
    else             g_V16[b][s][tid] = h;
    if (p < 2) {
        __shared__ float r[256];
        r[tid] = v * v;
        __syncthreads();
        for (int off = 128; off > 0; off >>= 1) {
            if (tid < off) r[tid] += r[tid + off];
            __syncthreads();
        }
        if (tid == 0) {
            if (p == 0) g_q2[b][s] = r[0];
            else        g_k2[b][s] = r[0];
        }
    }
}

// --------------------------------------------------------------------------
// Inclusive prefix sum of V over t, per (b, column)
__global__ __launch_bounds__(256) void prefix_kernel() {
    int col = blockIdx.x;
    int b   = blockIdx.y;
    int tid = threadIdx.x;
    __shared__ float sb[256];
    float carry = 0.f;
    const float* V = &g_QKVf[b * 3 + 2][0][0];
    for (int t0 = 0; t0 < S; t0 += 256) {
        float x = V[(size_t)(t0 + tid) * KDIM + col];
        sb[tid] = x;
        __syncthreads();
        for (int off = 1; off < 256; off <<= 1) {
            float y = (tid >= off) ? sb[tid - off] : 0.f;
            __syncthreads();
            sb[tid] += y;
            __syncthreads();
        }
        g_cumV[b][t0 + tid][col] = carry + sb[tid];
        carry += sb[255];
        __syncthreads();
    }
}

// --------------------------------------------------------------------------
// Logits: re_qk via WMMA fp16 (K=256 concat), then
// logit = -softplus(tau)/sqrt(H) * log(nf^2 + q2+k2-2re + EPS), causal tiles only.
__global__ __launch_bounds__(256) void logits_kernel(const float* __restrict__ noise_floor,
                                                     const float* __restrict__ tau,
                                                     float* __restrict__ attn) {
    int jT = blockIdx.x, iT = blockIdx.y, b = blockIdx.z;
    if (jT > iT) return;
    __shared__ __align__(32) __half Ash[64][72];
    __shared__ __align__(32) __half Bsh[64][72];
    __shared__ __align__(32) float  Csh[64][72];
    int tid = threadIdx.x;
    int wid = tid >> 5;
    int wr = (wid >> 1) * 16;
    int wc = (wid & 1) * 32;
    wmma::fragment<wmma::accumulator, 16, 16, 16, float> c0, c1;
    wmma::fill_fragment(c0, 0.f);
    wmma::fill_fragment(c1, 0.f);
    int s0 = iT * 64, t0 = jT * 64;

    for (int kc = 0; kc < KDIM; kc += 64) {
#pragma unroll
        for (int it = 0; it < 2; it++) {
            int v = tid + it * 256;
            int r = v >> 3, c8 = (v & 7) * 8;
            *(uint4*)&Ash[r][c8] = *(const uint4*)&g_Q16[b][s0 + r][kc + c8];
            *(uint4*)&Bsh[r][c8] = *(const uint4*)&g_K16[b][t0 + r][kc + c8];
        }
        __syncthreads();
#pragma unroll
        for (int ks = 0; ks < 4; ks++) {
            wmma::fragment<wmma::matrix_a, 16, 16, 16, __half, wmma::row_major> af;
            wmma::load_matrix_sync(af, &Ash[wr][ks * 16], 72);
            wmma::fragment<wmma::matrix_b, 16, 16, 16, __half, wmma::col_major> bf;
            wmma::load_matrix_sync(bf, &Bsh[wc][ks * 16], 72);
            wmma::mma_sync(c0, af, bf, c0);
            wmma::load_matrix_sync(bf, &Bsh[wc + 16][ks * 16], 72);
            wmma::mma_sync(c1, af, bf, c1);
        }
        __syncthreads();
    }
    wmma::store_matrix_sync(&Csh[wr][wc], c0, 72, wmma::mem_row_major);
    wmma::store_matrix_sync(&Csh[wr][wc + 16], c1, 72, wmma::mem_row_major);
    __syncthreads();

    float t  = tau[0];
    float sp = (t > 20.f) ? t : log1pf(__expf(t));
    float coeff = -sp * rsqrtf((float)H);
    float nf = noise_floor[0];
    float nf2 = nf * nf;
    for (int idx = tid; idx < 64 * 64; idx += 256) {
        int r = idx >> 6, cc = idx & 63;
        int s = s0 + r, tcol = t0 + cc;
        float re = Csh[r][cc];
        float R2 = g_q2[b][s] + g_k2[b][tcol] - 2.f * re;
        float lg = coeff * __logf(nf2 + R2 + 1e-6f);
        attn[((size_t)(b * S + s)) * S + tcol] = lg;   // t>s within diag tile overwritten by softmax
    }
}

// --------------------------------------------------------------------------
// Row softmax: writes fp32 weights (zeros beyond diag) + fp16 deviation copy
__global__ __launch_bounds__(256) void softmax_kernel(float* __restrict__ attn) {
    int s = blockIdx.x, b = blockIdx.y;
    int tid = threadIdx.x;
    float* L = attn + ((size_t)(b * S + s)) * S;
    __shared__ float buf[S];
    __shared__ float red[256];
    int n = s + 1;

    for (int i = tid; i < n; i += 256) buf[i] = L[i];
    __syncthreads();

    float m = -1e30f;
    for (int i = tid; i < n; i += 256) m = fmaxf(m, buf[i]);
    red[tid] = m;
    __syncthreads();
    for (int off = 128; off > 0; off >>= 1) {
        if (tid < off) red[tid] = fmaxf(red[tid], red[tid + off]);
        __syncthreads();
    }
    m = red[0];
    __syncthreads();

    float sum = 0.f;
    for (int i = tid; i < n; i += 256) {
        float e = __expf(buf[i] - m);
        buf[i] = e;
        sum += e;
    }
    red[tid] = sum;
    __syncthreads();
    for (int off = 128; off > 0; off >>= 1) {
        if (tid < off) red[tid] += red[tid + off];
        __syncthreads();
    }
    sum = red[0];

    float inv = 1.f / sum;
    float c = 1.f / (float)n;
    for (int i = tid; i < S; i += 256) {
        if (i < n) {
            float w = buf[i] * inv;
            L[i] = w;
            g_P16[b][s][i] = __float2half((w - c) * 1024.f);
        } else {
            L[i] = 0.f;
            g_P16[b][s][i] = __float2half(0.f);
        }
    }
}

// --------------------------------------------------------------------------
// est = (dev @ V16)/1024 + cumV[s]/(s+1), WMMA fp16, triangular K range
__global__ __launch_bounds__(256) void pv_kernel() {
    int nT = blockIdx.x, mT = blockIdx.y, b = blockIdx.z;
    __shared__ __align__(32) __half Ash[64][72];
    __shared__ __align__(32) __half Bsh[64][72];
    __shared__ __align__(32) float  Csh[64][72];
    int tid = threadIdx.x;
    int wid = tid >> 5;
    int wr = (wid >> 1) * 16;
    int wc = (wid & 1) * 32;
    wmma::fragment<wmma::accumulator, 16, 16, 16, float> c0, c1;
    wmma::fill_fragment(c0, 0.f);
    wmma::fill_fragment(c1, 0.f);
    int s0 = mT * 64, n0 = nT * 64;

    for (int kt = 0; kt <= mT; kt++) {
        int k0 = kt * 64;
#pragma unroll
        for (int it = 0; it < 2; it++) {
            int v = tid + it * 256;
            int r = v >> 3, c8 = (v & 7) * 8;
            *(uint4*)&Ash[r][c8] = *(const uint4*)&g_P16[b][s0 + r][k0 + c8];
            *(uint4*)&Bsh[r][c8] = *(const uint4*)&g_V16[b][k0 + r][n0 + c8];
        }
        __syncthreads();
#pragma unroll
        for (int ks = 0; ks < 4; ks++) {
            wmma::fragment<wmma::matrix_a, 16, 16, 16, __half, wmma::row_major> af;
            wmma::load_matrix_sync(af, &Ash[wr][ks * 16], 72);
            wmma::fragment<wmma::matrix_b, 16, 16, 16, __half, wmma::row_major> bf;
            wmma::load_matrix_sync(bf, &Bsh[ks * 16][wc], 72);
            wmma::mma_sync(c0, af, bf, c0);
            wmma::load_matrix_sync(bf, &Bsh[ks * 16][wc + 16], 72);
            wmma::mma_sync(c1, af, bf, c1);
        }
        __syncthreads();
    }
    wmma::store_matrix_sync(&Csh[wr][wc], c0, 72, wmma::mem_row_major);
    wmma::store_matrix_sync(&Csh[wr][wc + 16], c1, 72, wmma::mem_row_major);
    __syncthreads();

    for (int idx = tid; idx < 64 * 64; idx += 256) {
        int r = idx >> 6, cc = idx & 63;
        int s = s0 + r;
        float est = Csh[r][cc] * (1.f / 1024.f)
                  + g_cumV[b][s][n0 + cc] / (float)(s + 1);
        g_est[b][s][n0 + cc] = est;
    }
}

// --------------------------------------------------------------------------
extern "C" void kernel_launch(void* const* d_in, const int* in_sizes, int n_in,
                              void* d_out, int out_size) {
    (void)in_sizes; (void)n_in; (void)out_size;
    const float* Zq = (const float*)d_in[0];
    const float* Zk = (const float*)d_in[1];
    const float* Zv = (const float*)d_in[2];
    const float* nf  = (const float*)d_in[19];
    const float* tau = (const float*)d_in[20];
    float* out  = (float*)d_out;                       // (B,2,S,H,1)
    float* attn = out + (size_t)BATCH * 2 * S * H;     // (B,S,S)

    // pack effective weights: q(3..6), k(7..10), v(11..14), p(15..18)
    pack_weights_kernel<<<256, 256>>>(0, (const float*)d_in[3],  (const float*)d_in[4],
                                         (const float*)d_in[5],  (const float*)d_in[6]);
    pack_weights_kernel<<<256, 256>>>(1, (const float*)d_in[7],  (const float*)d_in[8],
                                         (const float*)d_in[9],  (const float*)d_in[10]);
    pack_weights_kernel<<<256, 256>>>(2, (const float*)d_in[11], (const float*)d_in[12],
                                         (const float*)d_in[13], (const float*)d_in[14]);
    pack_weights_kernel<<<256, 256>>>(3, (const float*)d_in[15], (const float*)d_in[16],
                                         (const float*)d_in[17], (const float*)d_in[18]);

    proj_kernel<<<dim3(2, 32, BATCH * 3), 256>>>(Zq, Zk, Zv);
    convert_kernel<<<dim3(S, BATCH * 3), 256>>>();
    prefix_kernel<<<dim3(KDIM, BATCH), 256>>>();
    logits_kernel<<<dim3(64, 64, BATCH), 256>>>(nf, tau, attn);
    softmax_kernel<<<dim3(S, BATCH), 256>>>(attn);
    pv_kernel<<<dim3(4, 64, BATCH), 256>>>();
    outproj_kernel<<<dim3(2, 32, BATCH), 256>>>(out);
}

// round 6
// speedup vs baseline: 1.1469x; 1.1469x over previous
#include <cuda_runtime.h>
#include <cuda_fp16.h>
#include <mma.h>

using namespace nvcuda;

#define S 4096
#define D 128
#define H 128
#define BATCH 2
#define KDIM 256
#define FEPS 1e-6f
#define FULLMASK 0xffffffffu

// ----------------------------- scratch (device globals: allocation-free) ---
__device__ __half g_Whi[4][KDIM][KDIM];
__device__ __half g_Wlo[4][KDIM][KDIM];
__device__ float  g_beff[4][KDIM];
__device__ __half g_Q16[BATCH][S][KDIM];
__device__ __half g_K16[BATCH][S][KDIM];
__device__ __half g_V16[BATCH][S][KDIM];
__device__ float  g_Vf[BATCH][S][KDIM];
__device__ float  g_q2[BATCH][S];
__device__ float  g_k2[BATCH][S];
__device__ float  g_cumV[BATCH][S][KDIM];
__device__ float  g_chunk[BATCH][32][KDIM];
__device__ __half g_P16[BATCH][S][S];       // (w - 1/(s+1)) * 1024
__device__ float  g_est[BATCH][S][KDIM];

// --------------------------------------------------------------------------
// Pack all 4 effective weights (fp16 hi/lo split) + biases; zero q2/k2.
//  out_r(j<128):  k<128 -> Wr[j][k],  k>=128 -> -Wi[j][k-128];  bias br-bi
//  out_i(j>=128): k<128 -> Wi[m][k],  k>=128 ->  Wr[m][k-128];  bias br+bi
__global__ void pack_all_kernel(
    const float* __restrict__ Wq_r, const float* __restrict__ Wq_i,
    const float* __restrict__ bq_r, const float* __restrict__ bq_i,
    const float* __restrict__ Wk_r, const float* __restrict__ Wk_i,
    const float* __restrict__ bk_r, const float* __restrict__ bk_i,
    const float* __restrict__ Wv_r, const float* __restrict__ Wv_i,
    const float* __restrict__ bv_r, const float* __restrict__ bv_i,
    const float* __restrict__ Wp_r, const float* __restrict__ Wp_i,
    const float* __restrict__ bp_r, const float* __restrict__ bp_i) {
    int p = blockIdx.y, k = blockIdx.x, j = threadIdx.x;
    const float *Wr, *Wi, *br, *bi;
    switch (p) {
        case 0:  Wr = Wq_r; Wi = Wq_i; br = bq_r; bi = bq_i; break;
        case 1:  Wr = Wk_r; Wi = Wk_i; br = bk_r; bi = bk_i; break;
        case 2:  Wr = Wv_r; Wi = Wv_i; br = bv_r; bi = bv_i; break;
        default: Wr = Wp_r; Wi = Wp_i; br = bp_r; bi = bp_i; break;
    }
    float w;
    if (j < 128) {
        w = (k < 128) ? Wr[j * D + k] : -Wi[j * D + (k - 128)];
    } else {
        int m = j - 128;
        w = (k < 128) ? Wi[m * D + k] : Wr[m * D + (k - 128)];
    }
    __half hi = __float2half(w);
    g_Whi[p][k][j] = hi;
    g_Wlo[p][k][j] = __float2half((w - __half2float(hi)) * 2048.f);
    if (k == 0) {
        g_beff[p][j] = (j < 128) ? (br[j] - bi[j]) : (br[j - 128] + bi[j - 128]);
    }
    if (p == 0 && k < 64) {
        int idx = k * 256 + j;                 // 0..16383
        if (idx < BATCH * S) ((float*)g_q2)[idx] = 0.f;
        else                 ((float*)g_k2)[idx - BATCH * S] = 0.f;
    }
}

// --------------------------------------------------------------------------
// fp16-split WMMA GEMM: C[128x128] = A[.,256] x W[256,256] + bias  (~fp32 acc)
// MODE 0: A from Z planes (plane = k>>7); epilogue by p (Q16/K16/V16,q2/k2,Vf)
// MODE 1: A contiguous [S][KDIM]; epilogue -> d_out complex mapping
union SplitSmem {
    struct {
        __half Ahi[128][40];
        __half Alo[128][40];
        __half Bhi[32][136];
        __half Blo[32][136];
    } g;                        // 37888 B
    float stage[8][16][68];     // 34816 B
};

template <int MODE>
__device__ __forceinline__ void gemm_split(const float* __restrict__ Abase,
                                           const __half* __restrict__ Whi,
                                           const __half* __restrict__ Wlo,
                                           const float* __restrict__ bias,
                                           int b, int p, float* __restrict__ outp) {
    __shared__ __align__(16) SplitSmem sm;
    int s0 = blockIdx.y * 128, j0 = blockIdx.x * 128;
    int tid = threadIdx.x, lane = tid & 31, wid = tid >> 5;
    int wr = wid >> 1, wc = wid & 1;  // warp tile: rows wr*32, cols wc*64

    wmma::fragment<wmma::accumulator, 16, 16, 16, float> mainf[2][4], corrf[2][4];
#pragma unroll
    for (int i = 0; i < 2; i++)
#pragma unroll
        for (int j = 0; j < 4; j++) {
            wmma::fill_fragment(mainf[i][j], 0.f);
            wmma::fill_fragment(corrf[i][j], 0.f);
        }

    for (int kc = 0; kc < KDIM; kc += 32) {
        // A chunk: 128 rows x 32 cols fp32 -> split hi/lo
#pragma unroll
        for (int it = 0; it < 4; it++) {
            int v = tid + it * 256;     // 0..1023
            int r = v >> 3, c4 = (v & 7) * 4;
            int kk = kc + c4;
            const float* src;
            if (MODE == 0)
                src = Abase + (size_t)(kk >> 7) * (S * D) + (size_t)(s0 + r) * D + (kk & 127);
            else
                src = Abase + (size_t)(s0 + r) * KDIM + kk;
            float4 a = *(const float4*)src;
            __half h0 = __float2half(a.x), h1 = __float2half(a.y);
            __half h2 = __float2half(a.z), h3 = __float2half(a.w);
            sm.g.Ahi[r][c4 + 0] = h0; sm.g.Ahi[r][c4 + 1] = h1;
            sm.g.Ahi[r][c4 + 2] = h2; sm.g.Ahi[r][c4 + 3] = h3;
            sm.g.Alo[r][c4 + 0] = __float2half((a.x - __half2float(h0)) * 2048.f);
            sm.g.Alo[r][c4 + 1] = __float2half((a.y - __half2float(h1)) * 2048.f);
            sm.g.Alo[r][c4 + 2] = __float2half((a.z - __half2float(h2)) * 2048.f);
            sm.g.Alo[r][c4 + 3] = __float2half((a.w - __half2float(h3)) * 2048.f);
        }
        // B chunk: 32 rows x 128 cols (pre-split halves)
#pragma unroll
        for (int it = 0; it < 2; it++) {
            int v = tid + it * 256;     // 0..511
            int r = v >> 4, c8 = (v & 15) * 8;
            *(uint4*)&sm.g.Bhi[r][c8] = *(const uint4*)&Whi[(size_t)(kc + r) * KDIM + j0 + c8];
            *(uint4*)&sm.g.Blo[r][c8] = *(const uint4*)&Wlo[(size_t)(kc + r) * KDIM + j0 + c8];
        }
        __syncthreads();
#pragma unroll
        for (int ks = 0; ks < 2; ks++) {
            int k = ks * 16;
            wmma::fragment<wmma::matrix_a, 16, 16, 16, __half, wmma::row_major> ahi[2], alo[2];
#pragma unroll
            for (int i = 0; i < 2; i++) {
                wmma::load_matrix_sync(ahi[i], &sm.g.Ahi[wr * 32 + i * 16][k], 40);
                wmma::load_matrix_sync(alo[i], &sm.g.Alo[wr * 32 + i * 16][k], 40);
            }
#pragma unroll
            for (int j = 0; j < 4; j++) {
                wmma::fragment<wmma::matrix_b, 16, 16, 16, __half, wmma::row_major> bh, bl;
                wmma::load_matrix_sync(bh, &sm.g.Bhi[k][wc * 64 + j * 16], 136);
                wmma::load_matrix_sync(bl, &sm.g.Blo[k][wc * 64 + j * 16], 136);
#pragma unroll
                for (int i = 0; i < 2; i++) {
                    wmma::mma_sync(mainf[i][j], ahi[i], bh, mainf[i][j]);
                    wmma::mma_sync(corrf[i][j], ahi[i], bl, corrf[i][j]);
                    wmma::mma_sync(corrf[i][j], alo[i], bh, corrf[i][j]);
                }
            }
        }
        __syncthreads();
    }

    // epilogue (per-warp staging; smem free after last sync)
#pragma unroll
    for (int i = 0; i < 2; i++) {
#pragma unroll
        for (int j = 0; j < 4; j++) {
#pragma unroll
            for (int e = 0; e < mainf[i][j].num_elements; e++)
                mainf[i][j].x[e] += corrf[i][j].x[e] * (1.f / 2048.f);
            wmma::store_matrix_sync(&sm.stage[wid][0][j * 16], mainf[i][j], 68,
                                    wmma::mem_row_major);
        }
        __syncwarp();
        int row = lane >> 1, colh = lane & 1;
        int s = s0 + wr * 32 + i * 16 + row;
        float sq = 0.f;
#pragma unroll
        for (int c = 0; c < 32; c++) {
            int lc = colh * 32 + c;
            int jj = j0 + wc * 64 + lc;
            float v = sm.stage[wid][row][lc] + bias[jj];
            if (MODE == 0) {
                __half h = __float2half(v);
                if (p == 0)      { g_Q16[b][s][jj] = h; sq += v * v; }
                else if (p == 1) { g_K16[b][s][jj] = h; sq += v * v; }
                else             { g_V16[b][s][jj] = h; g_Vf[b][s][jj] = v; }
            } else {
                outp[((size_t)(b * 2 + (jj >> 7)) * S + s) * H + (jj & 127)] = v;
            }
        }
        if (MODE == 0 && p < 2) {
            sq += __shfl_xor_sync(FULLMASK, sq, 1);
            if (colh == 0) {
                if (p == 0) atomicAdd(&g_q2[b][s], sq);
                else        atomicAdd(&g_k2[b][s], sq);
            }
        }
        __syncwarp();
    }
}

__global__ __launch_bounds__(256) void proj_kernel(const float* __restrict__ Zq,
                                                   const float* __restrict__ Zk,
                                                   const float* __restrict__ Zv) {
    int z = blockIdx.z;
    int b = z / 3, p = z % 3;
    const float* Zb = ((p == 0) ? Zq : (p == 1) ? Zk : Zv) + (size_t)b * 2 * S * D;
    gemm_split<0>(Zb, &g_Whi[p][0][0], &g_Wlo[p][0][0], g_beff[p], b, p, nullptr);
}

__global__ __launch_bounds__(256) void outproj_kernel(float* __restrict__ out) {
    int b = blockIdx.z;
    gemm_split<1>(&g_est[b][0][0], &g_Whi[3][0][0], &g_Wlo[3][0][0], g_beff[3], b, 0, out);
}

// --------------------------------------------------------------------------
// Hierarchical prefix sum of V over t (coalesced: thread <-> column)
__global__ __launch_bounds__(256) void prefix1_kernel() {
    int ch = blockIdx.x, b = blockIdx.y, col = threadIdx.x;
    const float* V = &g_Vf[b][ch * 128][0];
    float s = 0.f;
#pragma unroll 8
    for (int r = 0; r < 128; r++) s += V[(size_t)r * KDIM + col];
    g_chunk[b][ch][col] = s;
}

__global__ __launch_bounds__(256) void prefix2_kernel() {
    int b = blockIdx.x, col = threadIdx.x;
    float c = 0.f;
#pragma unroll
    for (int ch = 0; ch < 32; ch++) {
        float t = g_chunk[b][ch][col];
        g_chunk[b][ch][col] = c;
        c += t;
    }
}

__global__ __launch_bounds__(256) void prefix3_kernel() {
    int ch = blockIdx.x, b = blockIdx.y, col = threadIdx.x;
    float c = g_chunk[b][ch][col];
    const float* V = &g_Vf[b][ch * 128][0];
    float* C = &g_cumV[b][ch * 128][0];
#pragma unroll 4
    for (int r = 0; r < 128; r++) {
        c += V[(size_t)r * KDIM + col];
        C[(size_t)r * KDIM + col] = c;
    }
}

// --------------------------------------------------------------------------
// Logits: 128x128 tiles. Lower/diag: WMMA re_qk + log epilogue.
// Upper: zero-fill attn (softmax only touches <= roundup(s+1,128)).
union LogSmem {
    struct {
        __half A[128][72];
        __half Bm[128][72];
    } g;                        // 36864 B
    float stage[8][16][68];     // 34816 B
};

__global__ __launch_bounds__(256) void logits_kernel(const float* __restrict__ nf_,
                                                     const float* __restrict__ tau_,
                                                     float* __restrict__ attn) {
    int jT = blockIdx.x, iT = blockIdx.y, b = blockIdx.z;
    int s0 = iT * 128, t0 = jT * 128;
    int tid = threadIdx.x;

    if (jT > iT) {  // strict upper: zero attn
        float4 z = make_float4(0.f, 0.f, 0.f, 0.f);
#pragma unroll
        for (int it = 0; it < 16; it++) {
            int f = it * 256 + tid;     // 0..4095 float4s
            int r = f >> 5, c4 = (f & 31) * 4;
            *(float4*)&attn[((size_t)(b * S + s0 + r)) * S + t0 + c4] = z;
        }
        return;
    }

    __shared__ __align__(16) LogSmem sm;
    int lane = tid & 31, wid = tid >> 5;
    int wr = wid >> 1, wc = wid & 1;
    wmma::fragment<wmma::accumulator, 16, 16, 16, float> acc[2][4];
#pragma unroll
    for (int i = 0; i < 2; i++)
#pragma unroll
        for (int j = 0; j < 4; j++) wmma::fill_fragment(acc[i][j], 0.f);

    for (int kc = 0; kc < KDIM; kc += 64) {
#pragma unroll
        for (int it = 0; it < 4; it++) {
            int v = tid + it * 256;     // 0..1023
            int r = v >> 3, c8 = (v & 7) * 8;
            *(uint4*)&sm.g.A[r][c8]  = *(const uint4*)&g_Q16[b][s0 + r][kc + c8];
            *(uint4*)&sm.g.Bm[r][c8] = *(const uint4*)&g_K16[b][t0 + r][kc + c8];
        }
        __syncthreads();
#pragma unroll
        for (int ks = 0; ks < 4; ks++) {
            int k = ks * 16;
            wmma::fragment<wmma::matrix_a, 16, 16, 16, __half, wmma::row_major> a[2];
#pragma unroll
            for (int i = 0; i < 2; i++)
                wmma::load_matrix_sync(a[i], &sm.g.A[wr * 32 + i * 16][k], 72);
#pragma unroll
            for (int j = 0; j < 4; j++) {
                wmma::fragment<wmma::matrix_b, 16, 16, 16, __half, wmma::col_major> bf;
                wmma::load_matrix_sync(bf, &sm.g.Bm[wc * 64 + j * 16][k], 72);
#pragma unroll
                for (int i = 0; i < 2; i++) wmma::mma_sync(acc[i][j], a[i], bf, acc[i][j]);
            }
        }
        __syncthreads();
    }

    float tv = tau_[0];
    float sp = (tv > 20.f) ? tv : log1pf(__expf(tv));
    float coeff = -sp * 0.08838834764831845f;   // softplus(tau)/sqrt(H)
    float nf = nf_[0];
    float nf2 = nf * nf + FEPS;

#pragma unroll
    for (int i = 0; i < 2; i++) {
#pragma unroll
        for (int j = 0; j < 4; j++)
            wmma::store_matrix_sync(&sm.stage[wid][0][j * 16], acc[i][j], 68,
                                    wmma::mem_row_major);
        __syncwarp();
        int row = lane >> 1, colh = lane & 1;
        int s = s0 + wr * 32 + i * 16 + row;
        float q2s = g_q2[b][s];
        size_t rowbase = ((size_t)(b * S + s)) * S;
#pragma unroll
        for (int c4 = 0; c4 < 8; c4++) {
            int lc = colh * 32 + c4 * 4;
            int t = t0 + wc * 64 + lc;
            float4 re = *(float4*)&sm.stage[wid][row][lc];
            float4 o;
            o.x = coeff * __logf(nf2 + q2s + g_k2[b][t + 0] - 2.f * re.x);
            o.y = coeff * __logf(nf2 + q2s + g_k2[b][t + 1] - 2.f * re.y);
            o.z = coeff * __logf(nf2 + q2s + g_k2[b][t + 2] - 2.f * re.z);
            o.w = coeff * __logf(nf2 + q2s + g_k2[b][t + 3] - 2.f * re.w);
            *(float4*)&attn[rowbase + t] = o;
        }
        __syncwarp();
    }
}

// --------------------------------------------------------------------------
// Row softmax: fp32 weights (zeros to roundup(s+1,128)) + fp16 deviation copy
__global__ __launch_bounds__(256) void softmax_kernel(float* __restrict__ attn) {
    int s = blockIdx.x, b = blockIdx.y;
    int tid = threadIdx.x;
    float* L = attn + ((size_t)(b * S + s)) * S;
    __shared__ float buf[S];
    __shared__ float red[256];
    int n = s + 1;
    int kend = ((s >> 7) + 1) << 7;

    for (int i = tid; i < n; i += 256) buf[i] = L[i];
    __syncthreads();

    float m = -1e30f;
    for (int i = tid; i < n; i += 256) m = fmaxf(m, buf[i]);
    red[tid] = m;
    __syncthreads();
    for (int off = 128; off > 0; off >>= 1) {
        if (tid < off) red[tid] = fmaxf(red[tid], red[tid + off]);
        __syncthreads();
    }
    m = red[0];
    __syncthreads();

    float sum = 0.f;
    for (int i = tid; i < n; i += 256) {
        float e = __expf(buf[i] - m);
        buf[i] = e;
        sum += e;
    }
    red[tid] = sum;
    __syncthreads();
    for (int off = 128; off > 0; off >>= 1) {
        if (tid < off) red[tid] += red[tid + off];
        __syncthreads();
    }
    sum = red[0];

    float inv = 1.f / sum;
    float c = 1.f / (float)n;
    for (int i = tid; i < kend; i += 256) {
        if (i < n) {
            float w = buf[i] * inv;
            L[i] = w;
            g_P16[b][s][i] = __float2half((w - c) * 1024.f);
        } else {
            L[i] = 0.f;
            g_P16[b][s][i] = __float2half(0.f);
        }
    }
}

// --------------------------------------------------------------------------
// est = (dev @ V16)/1024 + cumV[s]/(s+1); tiles 64(M) x 128(N), triangular K
union PvSmem {
    struct {
        __half A[64][72];
        __half Bm[64][136];
    } g;                        // 26624 B
    float stage[8][16][20];     // 10240 B
};

__global__ __launch_bounds__(256) void pv_kernel() {
    int nT = blockIdx.x, mT = blockIdx.y, b = blockIdx.z;
    int s0 = mT * 64, n0 = nT * 128;
    __shared__ __align__(16) PvSmem sm;
    int tid = threadIdx.x, lane = tid & 31, wid = tid >> 5;
    int wr = wid >> 2, wcc = wid & 3;   // warp tile: rows wr*32, cols wcc*32
    wmma::fragment<wmma::accumulator, 16, 16, 16, float> acc[2][2];
#pragma unroll
    for (int i = 0; i < 2; i++)
#pragma unroll
        for (int j = 0; j < 2; j++) wmma::fill_fragment(acc[i][j], 0.f);

    int kend = (((s0 + 64) + 127) >> 7) << 7;   // matches softmax P16 zero region
    for (int k0 = 0; k0 < kend; k0 += 64) {
#pragma unroll
        for (int it = 0; it < 2; it++) {
            int v = tid + it * 256;     // 0..511
            int r = v >> 3, c8 = (v & 7) * 8;
            *(uint4*)&sm.g.A[r][c8] = *(const uint4*)&g_P16[b][s0 + r][k0 + c8];
        }
#pragma unroll
        for (int it = 0; it < 4; it++) {
            int v = tid + it * 256;     // 0..1023
            int r = v >> 4, c8 = (v & 15) * 8;
            *(uint4*)&sm.g.Bm[r][c8] = *(const uint4*)&g_V16[b][k0 + r][n0 + c8];
        }
        __syncthreads();
#pragma unroll
        for (int ks = 0; ks < 4; ks++) {
            int k = ks * 16;
            wmma::fragment<wmma::matrix_a, 16, 16, 16, __half, wmma::row_major> a[2];
#pragma unroll
            for (int i = 0; i < 2; i++)
                wmma::load_matrix_sync(a[i], &sm.g.A[wr * 32 + i * 16][k], 72);
#pragma unroll
            for (int j = 0; j < 2; j++) {
                wmma::fragment<wmma::matrix_b, 16, 16, 16, __half, wmma::row_major> bf;
                wmma::load_matrix_sync(bf, &sm.g.Bm[k][wcc * 32 + j * 16], 136);
#pragma unroll
                for (int i = 0; i < 2; i++) wmma::mma_sync(acc[i][j], a[i], bf, acc[i][j]);
            }
        }
        __syncthreads();
    }

#pragma unroll
    for (int i = 0; i < 2; i++) {
#pragma unroll
        for (int j = 0; j < 2; j++) {
            wmma::store_matrix_sync(&sm.stage[wid][0][0], acc[i][j], 20, wmma::mem_row_major);
            __syncwarp();
            int row = lane >> 1, colh = lane & 1;
            int s = s0 + wr * 32 + i * 16 + row;
            float invn = 1.f / (float)(s + 1);
            int nb = n0 + wcc * 32 + j * 16 + colh * 8;
#pragma unroll
            for (int c = 0; c < 8; c++) {
                float v = sm.stage[wid][row][colh * 8 + c] * (1.f / 1024.f)
                        + g_cumV[b][s][nb + c] * invn;
                g_est[b][s][nb + c] = v;
            }
            __syncwarp();
        }
    }
}

// --------------------------------------------------------------------------
extern "C" void kernel_launch(void* const* d_in, const int* in_sizes, int n_in,
                              void* d_out, int out_size) {
    (void)in_sizes; (void)n_in; (void)out_size;
    const float* Zq  = (const float*)d_in[0];
    const float* Zk  = (const float*)d_in[1];
    const float* Zv  = (const float*)d_in[2];
    const float* nf  = (const float*)d_in[19];
    const float* tau = (const float*)d_in[20];
    float* out  = (float*)d_out;                    // (B,2,S,H,1)
    float* attn = out + (size_t)BATCH * 2 * S * H;  // (B,S,S)

    pack_all_kernel<<<dim3(256, 4), 256>>>(
        (const float*)d_in[3],  (const float*)d_in[4],  (const float*)d_in[5],  (const float*)d_in[6],
        (const float*)d_in[7],  (const float*)d_in[8],  (const float*)d_in[9],  (const float*)d_in[10],
        (const float*)d_in[11], (const float*)d_in[12], (const float*)d_in[13], (const float*)d_in[14],
        (const float*)d_in[15], (const float*)d_in[16], (const float*)d_in[17], (const float*)d_in[18]);

    proj_kernel<<<dim3(2, 32, BATCH * 3), 256>>>(Zq, Zk, Zv);
    prefix1_kernel<<<dim3(32, BATCH), 256>>>();
    prefix2_kernel<<<BATCH, 256>>>();
    prefix3_kernel<<<dim3(32, BATCH), 256>>>();
    logits_kernel<<<dim3(32, 32, BATCH), 256>>>(nf, tau, attn);
    softmax_kernel<<<dim3(S, BATCH), 256>>>(attn);
    pv_kernel<<<dim3(2, 64, BATCH), 256>>>();
    outproj_kernel<<<dim3(2, 32, BATCH), 256>>>(out);
}

// round 7
// speedup vs baseline: 1.2784x; 1.1147x over previous
#include <cuda_runtime.h>
#include <cuda_fp16.h>
#include <mma.h>

using namespace nvcuda;

#define S 4096
#define D 128
#define H 128
#define BATCH 2
#define KDIM 256
#define FEPS 1e-6f
#define FULLMASK 0xffffffffu

// ----------------------------- scratch (device globals: allocation-free) ---
__device__ __half g_Whi[4][KDIM][KDIM];
__device__ __half g_Wlo[4][KDIM][KDIM];
__device__ float  g_beff[4][KDIM];
__device__ __half g_Q16[BATCH][S][KDIM];
__device__ __half g_K16[BATCH][S][KDIM];
__device__ __half g_V16[BATCH][S][KDIM];
__device__ float  g_Vf[BATCH][S][KDIM];
__device__ float  g_q2[BATCH][S];
__device__ float  g_k2[BATCH][S];
__device__ float  g_rowsum[BATCH][S];
__device__ float  g_cumV[BATCH][S][KDIM];
__device__ float  g_chunk[BATCH][32][KDIM];
__device__ __half g_P16[BATCH][S][S];       // (w - 1/(s+1)) * 1024
__device__ float  g_est[BATCH][S][KDIM];

// --------------------------------------------------------------------------
// Pack all 4 effective weights (fp16 hi/lo split) + biases; zero q2/k2/rowsum.
__global__ void pack_all_kernel(
    const float* __restrict__ Wq_r, const float* __restrict__ Wq_i,
    const float* __restrict__ bq_r, const float* __restrict__ bq_i,
    const float* __restrict__ Wk_r, const float* __restrict__ Wk_i,
    const float* __restrict__ bk_r, const float* __restrict__ bk_i,
    const float* __restrict__ Wv_r, const float* __restrict__ Wv_i,
    const float* __restrict__ bv_r, const float* __restrict__ bv_i,
    const float* __restrict__ Wp_r, const float* __restrict__ Wp_i,
    const float* __restrict__ bp_r, const float* __restrict__ bp_i) {
    int p = blockIdx.y, k = blockIdx.x, j = threadIdx.x;
    const float *Wr, *Wi, *br, *bi;
    switch (p) {
        case 0:  Wr = Wq_r; Wi = Wq_i; br = bq_r; bi = bq_i; break;
        case 1:  Wr = Wk_r; Wi = Wk_i; br = bk_r; bi = bk_i; break;
        case 2:  Wr = Wv_r; Wi = Wv_i; br = bv_r; bi = bv_i; break;
        default: Wr = Wp_r; Wi = Wp_i; br = bp_r; bi = bp_i; break;
    }
    float w;
    if (j < 128) {
        w = (k < 128) ? Wr[j * D + k] : -Wi[j * D + (k - 128)];
    } else {
        int m = j - 128;
        w = (k < 128) ? Wi[m * D + k] : Wr[m * D + (k - 128)];
    }
    __half hi = __float2half(w);
    g_Whi[p][k][j] = hi;
    g_Wlo[p][k][j] = __float2half((w - __half2float(hi)) * 2048.f);
    if (k == 0) {
        g_beff[p][j] = (j < 128) ? (br[j] - bi[j]) : (br[j - 128] + bi[j - 128]);
    }
    if (p == 0 && k < 96) {
        int idx = k * 256 + j;                 // 0..24575
        if (idx < BATCH * S)          ((float*)g_q2)[idx] = 0.f;
        else if (idx < 2 * BATCH * S) ((float*)g_k2)[idx - BATCH * S] = 0.f;
        else                          ((float*)g_rowsum)[idx - 2 * BATCH * S] = 0.f;
    }
}

// --------------------------------------------------------------------------
// WMMA GEMM: C[128x128] = A[.,256] x W[256,256] + bias
// SPLIT=true: fp16 hi/lo split (~fp32 accuracy, 3 MMAs); false: plain fp16 (1 MMA)
// MODE 0: A from Z planes (plane = k>>7); epilogue by p (Q16/K16/V16,q2/k2,Vf)
// MODE 1: A contiguous [S][KDIM]; epilogue -> d_out complex mapping
union SplitSmem {
    struct {
        __half Ahi[128][40];
        __half Alo[128][40];
        __half Bhi[32][136];
        __half Blo[32][136];
    } g;                        // 37888 B
    float stage[8][16][68];     // 34816 B
};

template <int MODE, bool SPLIT>
__device__ __forceinline__ void gemm_split(const float* __restrict__ Abase,
                                           const __half* __restrict__ Whi,
                                           const __half* __restrict__ Wlo,
                                           const float* __restrict__ bias,
                                           int b, int p, float* __restrict__ outp) {
    __shared__ __align__(16) SplitSmem sm;
    int s0 = blockIdx.y * 128, j0 = blockIdx.x * 128;
    int tid = threadIdx.x, lane = tid & 31, wid = tid >> 5;
    int wr = wid >> 1, wc = wid & 1;  // warp tile: rows wr*32, cols wc*64

    wmma::fragment<wmma::accumulator, 16, 16, 16, float> mainf[2][4], corrf[2][4];
#pragma unroll
    for (int i = 0; i < 2; i++)
#pragma unroll
        for (int j = 0; j < 4; j++) {
            wmma::fill_fragment(mainf[i][j], 0.f);
            if (SPLIT) wmma::fill_fragment(corrf[i][j], 0.f);
        }

    for (int kc = 0; kc < KDIM; kc += 32) {
        // A chunk: 128 rows x 32 cols fp32 -> fp16 (hi, + lo if SPLIT)
#pragma unroll
        for (int it = 0; it < 4; it++) {
            int v = tid + it * 256;     // 0..1023
            int r = v >> 3, c4 = (v & 7) * 4;
            int kk = kc + c4;
            const float* src;
            if (MODE == 0)
                src = Abase + (size_t)(kk >> 7) * (S * D) + (size_t)(s0 + r) * D + (kk & 127);
            else
                src = Abase + (size_t)(s0 + r) * KDIM + kk;
            float4 a = *(const float4*)src;
            __half h0 = __float2half(a.x), h1 = __float2half(a.y);
            __half h2 = __float2half(a.z), h3 = __float2half(a.w);
            sm.g.Ahi[r][c4 + 0] = h0; sm.g.Ahi[r][c4 + 1] = h1;
            sm.g.Ahi[r][c4 + 2] = h2; sm.g.Ahi[r][c4 + 3] = h3;
            if (SPLIT) {
                sm.g.Alo[r][c4 + 0] = __float2half((a.x - __half2float(h0)) * 2048.f);
                sm.g.Alo[r][c4 + 1] = __float2half((a.y - __half2float(h1)) * 2048.f);
                sm.g.Alo[r][c4 + 2] = __float2half((a.z - __half2float(h2)) * 2048.f);
                sm.g.Alo[r][c4 + 3] = __float2half((a.w - __half2float(h3)) * 2048.f);
            }
        }
        // B chunk: 32 rows x 128 cols
#pragma unroll
        for (int it = 0; it < 2; it++) {
            int v = tid + it * 256;     // 0..511
            int r = v >> 4, c8 = (v & 15) * 8;
            *(uint4*)&sm.g.Bhi[r][c8] = *(const uint4*)&Whi[(size_t)(kc + r) * KDIM + j0 + c8];
            if (SPLIT)
                *(uint4*)&sm.g.Blo[r][c8] = *(const uint4*)&Wlo[(size_t)(kc + r) * KDIM + j0 + c8];
        }
        __syncthreads();
#pragma unroll
        for (int ks = 0; ks < 2; ks++) {
            int k = ks * 16;
            wmma::fragment<wmma::matrix_a, 16, 16, 16, __half, wmma::row_major> ahi[2], alo[2];
#pragma unroll
            for (int i = 0; i < 2; i++) {
                wmma::load_matrix_sync(ahi[i], &sm.g.Ahi[wr * 32 + i * 16][k], 40);
                if (SPLIT) wmma::load_matrix_sync(alo[i], &sm.g.Alo[wr * 32 + i * 16][k], 40);
            }
#pragma unroll
            for (int j = 0; j < 4; j++) {
                wmma::fragment<wmma::matrix_b, 16, 16, 16, __half, wmma::row_major> bh, bl;
                wmma::load_matrix_sync(bh, &sm.g.Bhi[k][wc * 64 + j * 16], 136);
                if (SPLIT) wmma::load_matrix_sync(bl, &sm.g.Blo[k][wc * 64 + j * 16], 136);
#pragma unroll
                for (int i = 0; i < 2; i++) {
                    wmma::mma_sync(mainf[i][j], ahi[i], bh, mainf[i][j]);
                    if (SPLIT) {
                        wmma::mma_sync(corrf[i][j], ahi[i], bl, corrf[i][j]);
                        wmma::mma_sync(corrf[i][j], alo[i], bh, corrf[i][j]);
                    }
                }
            }
        }
        __syncthreads();
    }

    // epilogue (per-warp staging; smem free after last sync)
#pragma unroll
    for (int i = 0; i < 2; i++) {
#pragma unroll
        for (int j = 0; j < 4; j++) {
            if (SPLIT) {
#pragma unroll
                for (int e = 0; e < mainf[i][j].num_elements; e++)
                    mainf[i][j].x[e] += corrf[i][j].x[e] * (1.f / 2048.f);
            }
            wmma::store_matrix_sync(&sm.stage[wid][0][j * 16], mainf[i][j], 68,
                                    wmma::mem_row_major);
        }
        __syncwarp();
        int row = lane >> 1, colh = lane & 1;
        int s = s0 + wr * 32 + i * 16 + row;
        float sq = 0.f;
#pragma unroll
        for (int c = 0; c < 32; c++) {
            int lc = colh * 32 + c;
            int jj = j0 + wc * 64 + lc;
            float v = sm.stage[wid][row][lc] + bias[jj];
            if (MODE == 0) {
                __half h = __float2half(v);
                if (p == 0)      { g_Q16[b][s][jj] = h; sq += v * v; }
                else if (p == 1) { g_K16[b][s][jj] = h; sq += v * v; }
                else             { g_V16[b][s][jj] = h; g_Vf[b][s][jj] = v; }
            } else {
                outp[((size_t)(b * 2 + (jj >> 7)) * S + s) * H + (jj & 127)] = v;
            }
        }
        if (MODE == 0 && p < 2) {
            sq += __shfl_xor_sync(FULLMASK, sq, 1);
            if (colh == 0) {
                if (p == 0) atomicAdd(&g_q2[b][s], sq);
                else        atomicAdd(&g_k2[b][s], sq);
            }
        }
        __syncwarp();
    }
}

// Q/K projections: plain fp16 (precision analysis: Q16/K16 are fp16 consumers,
// q2/k2 stay self-consistent with the rounded values)
__global__ __launch_bounds__(256) void projQK_kernel(const float* __restrict__ Zq,
                                                     const float* __restrict__ Zk) {
    int z = blockIdx.z;                 // 0..3
    int b = z >> 1, p = z & 1;
    const float* Zb = ((p == 0) ? Zq : Zk) + (size_t)b * 2 * S * D;
    gemm_split<0, false>(Zb, &g_Whi[p][0][0], &g_Wlo[p][0][0], g_beff[p], b, p, nullptr);
}

// V projection: full split (precision-critical est path)
__global__ __launch_bounds__(256) void projV_kernel(const float* __restrict__ Zv) {
    int b = blockIdx.z;
    const float* Zb = Zv + (size_t)b * 2 * S * D;
    gemm_split<0, true>(Zb, &g_Whi[2][0][0], &g_Wlo[2][0][0], g_beff[2], b, 2, nullptr);
}

__global__ __launch_bounds__(256) void outproj_kernel(float* __restrict__ out) {
    int b = blockIdx.z;
    gemm_split<1, true>(&g_est[b][0][0], &g_Whi[3][0][0], &g_Wlo[3][0][0], g_beff[3], b, 0, out);
}

// --------------------------------------------------------------------------
// Hierarchical prefix sum of V over t (coalesced: thread <-> column)
__global__ __launch_bounds__(256) void prefix1_kernel() {
    int ch = blockIdx.x, b = blockIdx.y, col = threadIdx.x;
    const float* V = &g_Vf[b][ch * 128][0];
    float s = 0.f;
#pragma unroll 8
    for (int r = 0; r < 128; r++) s += V[(size_t)r * KDIM + col];
    g_chunk[b][ch][col] = s;
}

__global__ __launch_bounds__(256) void prefix3_kernel() {
    int ch = blockIdx.x, b = blockIdx.y, col = threadIdx.x;
    float c = 0.f;
    for (int c2 = 0; c2 < ch; c2++) c += g_chunk[b][c2][col];
    const float* V = &g_Vf[b][ch * 128][0];
    float* C = &g_cumV[b][ch * 128][0];
#pragma unroll 4
    for (int r = 0; r < 128; r++) {
        c += V[(size_t)r * KDIM + col];
        C[(size_t)r * KDIM + col] = c;
    }
}

// --------------------------------------------------------------------------
// Logits+exp: 128x128 tiles. Lower/diag: WMMA re_qk, epilogue stores
// e = exp(logit) into attn (logits <= 0, no max needed) and atomically
// accumulates row sums. Upper: zero-fill attn.
union LogSmem {
    struct {
        __half A[128][72];
        __half Bm[128][72];
    } g;                        // 36864 B
    float stage[8][16][68];     // 34816 B
};

__global__ __launch_bounds__(256) void logits_kernel(const float* __restrict__ nf_,
                                                     const float* __restrict__ tau_,
                                                     float* __restrict__ attn) {
    int jT = blockIdx.x, iT = blockIdx.y, b = blockIdx.z;
    int s0 = iT * 128, t0 = jT * 128;
    int tid = threadIdx.x;

    if (jT > iT) {  // strict upper: zero attn
        float4 z = make_float4(0.f, 0.f, 0.f, 0.f);
#pragma unroll
        for (int it = 0; it < 16; it++) {
            int f = it * 256 + tid;     // 0..4095 float4s
            int r = f >> 5, c4 = (f & 31) * 4;
            *(float4*)&attn[((size_t)(b * S + s0 + r)) * S + t0 + c4] = z;
        }
        return;
    }

    __shared__ __align__(16) LogSmem sm;
    int lane = tid & 31, wid = tid >> 5;
    int wr = wid >> 1, wc = wid & 1;
    wmma::fragment<wmma::accumulator, 16, 16, 16, float> acc[2][4];
#pragma unroll
    for (int i = 0; i < 2; i++)
#pragma unroll
        for (int j = 0; j < 4; j++) wmma::fill_fragment(acc[i][j], 0.f);

    for (int kc = 0; kc < KDIM; kc += 64) {
#pragma unroll
        for (int it = 0; it < 4; it++) {
            int v = tid + it * 256;     // 0..1023
            int r = v >> 3, c8 = (v & 7) * 8;
            *(uint4*)&sm.g.A[r][c8]  = *(const uint4*)&g_Q16[b][s0 + r][kc + c8];
            *(uint4*)&sm.g.Bm[r][c8] = *(const uint4*)&g_K16[b][t0 + r][kc + c8];
        }
        __syncthreads();
#pragma unroll
        for (int ks = 0; ks < 4; ks++) {
            int k = ks * 16;
            wmma::fragment<wmma::matrix_a, 16, 16, 16, __half, wmma::row_major> a[2];
#pragma unroll
            for (int i = 0; i < 2; i++)
                wmma::load_matrix_sync(a[i], &sm.g.A[wr * 32 + i * 16][k], 72);
#pragma unroll
            for (int j = 0; j < 4; j++) {
                wmma::fragment<wmma::matrix_b, 16, 16, 16, __half, wmma::col_major> bf;
                wmma::load_matrix_sync(bf, &sm.g.Bm[wc * 64 + j * 16][k], 72);
#pragma unroll
                for (int i = 0; i < 2; i++) wmma::mma_sync(acc[i][j], a[i], bf, acc[i][j]);
            }
        }
        __syncthreads();
    }

    float tv = tau_[0];
    float sp = (tv > 20.f) ? tv : log1pf(__expf(tv));
    float coeff = -sp * 0.08838834764831845f;   // softplus(tau)/sqrt(H)
    float nf = nf_[0];
    float nf2 = nf * nf + FEPS;
    bool diag = (jT == iT);

#pragma unroll
    for (int i = 0; i < 2; i++) {
#pragma unroll
        for (int j = 0; j < 4; j++)
            wmma::store_matrix_sync(&sm.stage[wid][0][j * 16], acc[i][j], 68,
                                    wmma::mem_row_major);
        __syncwarp();
        int row = lane >> 1, colh = lane & 1;
        int s = s0 + wr * 32 + i * 16 + row;
        float q2s = g_q2[b][s];
        size_t rowbase = ((size_t)(b * S + s)) * S;
        float esum = 0.f;
#pragma unroll
        for (int c4 = 0; c4 < 8; c4++) {
            int lc = colh * 32 + c4 * 4;
            int t = t0 + wc * 64 + lc;
            float4 re = *(float4*)&sm.stage[wid][row][lc];
            float4 o;
            o.x = __expf(coeff * __logf(nf2 + q2s + g_k2[b][t + 0] - 2.f * re.x));
            o.y = __expf(coeff * __logf(nf2 + q2s + g_k2[b][t + 1] - 2.f * re.y));
            o.z = __expf(coeff * __logf(nf2 + q2s + g_k2[b][t + 2] - 2.f * re.z));
            o.w = __expf(coeff * __logf(nf2 + q2s + g_k2[b][t + 3] - 2.f * re.w));
            if (diag) {
                if (t + 0 > s) o.x = 0.f;
                if (t + 1 > s) o.y = 0.f;
                if (t + 2 > s) o.z = 0.f;
                if (t + 3 > s) o.w = 0.f;
            }
            esum += (o.x + o.y) + (o.z + o.w);
            *(float4*)&attn[rowbase + t] = o;
        }
        esum += __shfl_xor_sync(FULLMASK, esum, 1);
        if (colh == 0) atomicAdd(&g_rowsum[b][s], esum);
        __syncwarp();
    }
}

// --------------------------------------------------------------------------
// Normalize: w = e / rowsum (streamed, no reductions); also write P16 deviation
__global__ __launch_bounds__(128) void normalize_kernel(float* __restrict__ attn) {
    int s = blockIdx.x, b = blockIdx.y;
    int tid = threadIdx.x;
    float inv = 1.f / g_rowsum[b][s];
    float c = 1.f / (float)(s + 1);
    int kend = ((s >> 7) + 1) << 7;
    float* L = attn + ((size_t)(b * S + s)) * S;
    __half* P = &g_P16[b][s][0];
    for (int i = tid * 4; i < kend; i += 512) {
        float4 e = *(float4*)&L[i];
        float4 w = make_float4(e.x * inv, e.y * inv, e.z * inv, e.w * inv);
        *(float4*)&L[i] = w;
        float p0 = (i + 0 <= s) ? (w.x - c) * 1024.f : 0.f;
        float p1 = (i + 1 <= s) ? (w.y - c) * 1024.f : 0.f;
        float p2 = (i + 2 <= s) ? (w.z - c) * 1024.f : 0.f;
        float p3 = (i + 3 <= s) ? (w.w - c) * 1024.f : 0.f;
        *(__half2*)&P[i]     = __floats2half2_rn(p0, p1);
        *(__half2*)&P[i + 2] = __floats2half2_rn(p2, p3);
    }
}

// --------------------------------------------------------------------------
// est = (dev @ V16)/1024 + cumV[s]/(s+1); tiles 64(M) x 128(N), triangular K
union PvSmem {
    struct {
        __half A[64][72];
        __half Bm[64][136];
    } g;                        // 26624 B
    float stage[8][16][20];     // 10240 B
};

__global__ __launch_bounds__(256) void pv_kernel() {
    int nT = blockIdx.x, mT = blockIdx.y, b = blockIdx.z;
    int s0 = mT * 64, n0 = nT * 128;
    __shared__ __align__(16) PvSmem sm;
    int tid = threadIdx.x, lane = tid & 31, wid = tid >> 5;
    int wr = wid >> 2, wcc = wid & 3;   // warp tile: rows wr*32, cols wcc*32
    wmma::fragment<wmma::accumulator, 16, 16, 16, float> acc[2][2];
#pragma unroll
    for (int i = 0; i < 2; i++)
#pragma unroll
        for (int j = 0; j < 2; j++) wmma::fill_fragment(acc[i][j], 0.f);

    int kend = (((s0 + 64) + 127) >> 7) << 7;   // matches P16 zero region
    for (int k0 = 0; k0 < kend; k0 += 64) {
#pragma unroll
        for (int it = 0; it < 2; it++) {
            int v = tid + it * 256;     // 0..511
            int r = v >> 3, c8 = (v & 7) * 8;
            *(uint4*)&sm.g.A[r][c8] = *(const uint4*)&g_P16[b][s0 + r][k0 + c8];
        }
#pragma unroll
        for (int it = 0; it < 4; it++) {
            int v = tid + it * 256;     // 0..1023
            int r = v >> 4, c8 = (v & 15) * 8;
            *(uint4*)&sm.g.Bm[r][c8] = *(const uint4*)&g_V16[b][k0 + r][n0 + c8];
        }
        __syncthreads();
#pragma unroll
        for (int ks = 0; ks < 4; ks++) {
            int k = ks * 16;
            wmma::fragment<wmma::matrix_a, 16, 16, 16, __half, wmma::row_major> a[2];
#pragma unroll
            for (int i = 0; i < 2; i++)
                wmma::load_matrix_sync(a[i], &sm.g.A[wr * 32 + i * 16][k], 72);
#pragma unroll
            for (int j = 0; j < 2; j++) {
                wmma::fragment<wmma::matrix_b, 16, 16, 16, __half, wmma::row_major> bf;
                wmma::load_matrix_sync(bf, &sm.g.Bm[k][wcc * 32 + j * 16], 136);
#pragma unroll
                for (int i = 0; i < 2; i++) wmma::mma_sync(acc[i][j], a[i], bf, acc[i][j]);
            }
        }
        __syncthreads();
    }

#pragma unroll
    for (int i = 0; i < 2; i++) {
#pragma unroll
        for (int j = 0; j < 2; j++) {
            wmma::store_matrix_sync(&sm.stage[wid][0][0], acc[i][j], 20, wmma::mem_row_major);
            __syncwarp();
            int row = lane >> 1, colh = lane & 1;
            int s = s0 + wr * 32 + i * 16 + row;
            float invn = 1.f / (float)(s + 1);
            int nb = n0 + wcc * 32 + j * 16 + colh * 8;
#pragma unroll
            for (int c = 0; c < 8; c++) {
                float v = sm.stage[wid][row][colh * 8 + c] * (1.f / 1024.f)
                        + g_cumV[b][s][nb + c] * invn;
                g_est[b][s][nb + c] = v;
            }
            __syncwarp();
        }
    }
}

// --------------------------------------------------------------------------
extern "C" void kernel_launch(void* const* d_in, const int* in_sizes, int n_in,
                              void* d_out, int out_size) {
    (void)in_sizes; (void)n_in; (void)out_size;
    const float* Zq  = (const float*)d_in[0];
    const float* Zk  = (const float*)d_in[1];
    const float* Zv  = (const float*)d_in[2];
    const float* nf  = (const float*)d_in[19];
    const float* tau = (const float*)d_in[20];
    float* out  = (float*)d_out;                    // (B,2,S,H,1)
    float* attn = out + (size_t)BATCH * 2 * S * H;  // (B,S,S)

    pack_all_kernel<<<dim3(256, 4), 256>>>(
        (const float*)d_in[3],  (const float*)d_in[4],  (const float*)d_in[5],  (const float*)d_in[6],
        (const float*)d_in[7],  (const float*)d_in[8],  (const float*)d_in[9],  (const float*)d_in[10],
        (const float*)d_in[11], (const float*)d_in[12], (const float*)d_in[13], (const float*)d_in[14],
        (const float*)d_in[15], (const float*)d_in[16], (const float*)d_in[17], (const float*)d_in[18]);

    projQK_kernel<<<dim3(2, 32, 4), 256>>>(Zq, Zk);
    projV_kernel<<<dim3(2, 32, BATCH), 256>>>(Zv);
    prefix1_kernel<<<dim3(32, BATCH), 256>>>();
    prefix3_kernel<<<dim3(32, BATCH), 256>>>();
    logits_kernel<<<dim3(32, 32, BATCH), 256>>>(nf, tau, attn);
    normalize_kernel<<<dim3(S, BATCH), 128>>>(attn);
    pv_kernel<<<dim3(2, 64, BATCH), 256>>>();
    outproj_kernel<<<dim3(2, 32, BATCH), 256>>>(out);
}

// round 9
// speedup vs baseline: 1.4247x; 1.1145x over previous
#include <cuda_runtime.h>
#include <cuda_fp16.h>
#include <cstdint>
#include <mma.h>

using namespace nvcuda;

#define S 4096
#define D 128
#define H 128
#define BATCH 2
#define KDIM 256
#define FEPS 1e-6f
#define FULLMASK 0xffffffffu

// ----------------------------- scratch (device globals: allocation-free) ---
__device__ __half g_Whi[4][KDIM][KDIM];
__device__ __half g_Wlo[4][KDIM][KDIM];
__device__ float  g_beff[4][KDIM];
__device__ __half g_Q16[BATCH][S][KDIM];
__device__ __half g_K16[BATCH][S][KDIM];
__device__ __half g_V16[BATCH][S][KDIM];
__device__ float  g_Vf[BATCH][S][KDIM];
__device__ float  g_q2[BATCH][S];
__device__ float  g_k2[BATCH][S];
__device__ float  g_rowsum[BATCH][S];
__device__ float  g_cumV[BATCH][S][KDIM];
__device__ float  g_chunk[BATCH][64][KDIM];
__device__ float  g_est[BATCH][S][KDIM];

// ----------------------------- cp.async helpers ----------------------------
__device__ __forceinline__ uint32_t smem_u32(const void* p) {
    uint32_t a;
    asm("{ .reg .u64 t; cvta.to.shared.u64 t, %1; cvt.u32.u64 %0, t; }" : "=r"(a) : "l"(p));
    return a;
}
__device__ __forceinline__ void cp16(uint32_t dst, const void* src) {
    asm volatile("cp.async.ca.shared.global [%0], [%1], 16;" :: "r"(dst), "l"(src) : "memory");
}
#define CP_COMMIT() asm volatile("cp.async.commit_group;" ::: "memory")
#define CP_WAIT()   asm volatile("cp.async.wait_group 0;" ::: "memory")

// --------------------------------------------------------------------------
// Pack all 4 effective weights (fp16 hi/lo split) + biases; zero q2/k2/rowsum.
__global__ void pack_all_kernel(
    const float* __restrict__ Wq_r, const float* __restrict__ Wq_i,
    const float* __restrict__ bq_r, const float* __restrict__ bq_i,
    const float* __restrict__ Wk_r, const float* __restrict__ Wk_i,
    const float* __restrict__ bk_r, const float* __restrict__ bk_i,
    const float* __restrict__ Wv_r, const float* __restrict__ Wv_i,
    const float* __restrict__ bv_r, const float* __restrict__ bv_i,
    const float* __restrict__ Wp_r, const float* __restrict__ Wp_i,
    const float* __restrict__ bp_r, const float* __restrict__ bp_i) {
    int p = blockIdx.y, k = blockIdx.x, j = threadIdx.x;
    const float *Wr, *Wi, *br, *bi;
    switch (p) {
        case 0:  Wr = Wq_r; Wi = Wq_i; br = bq_r; bi = bq_i; break;
        case 1:  Wr = Wk_r; Wi = Wk_i; br = bk_r; bi = bk_i; break;
        case 2:  Wr = Wv_r; Wi = Wv_i; br = bv_r; bi = bv_i; break;
        default: Wr = Wp_r; Wi = Wp_i; br = bp_r; bi = bp_i; break;
    }
    float w;
    if (j < 128) {
        w = (k < 128) ? Wr[j * D + k] : -Wi[j * D + (k - 128)];
    } else {
        int m = j - 128;
        w = (k < 128) ? Wi[m * D + k] : Wr[m * D + (k - 128)];
    }
    __half hi = __float2half(w);
    g_Whi[p][k][j] = hi;
    g_Wlo[p][k][j] = __float2half((w - __half2float(hi)) * 2048.f);
    if (k == 0) {
        g_beff[p][j] = (j < 128) ? (br[j] - bi[j]) : (br[j - 128] + bi[j - 128]);
    }
    if (p == 0 && k < 96) {
        int idx = k * 256 + j;                 // 0..24575
        if (idx < BATCH * S)          ((float*)g_q2)[idx] = 0.f;
        else if (idx < 2 * BATCH * S) ((float*)g_k2)[idx - BATCH * S] = 0.f;
        else                          ((float*)g_rowsum)[idx - 2 * BATCH * S] = 0.f;
    }
}

// --------------------------------------------------------------------------
// WMMA GEMM: C[128x128] = A[.,256] x W[256,256] + bias (projections / outproj)
union SplitSmem {
    struct {
        __half Ahi[128][40];
        __half Alo[128][40];
        __half Bhi[32][136];
        __half Blo[32][136];
    } g;
    float stage[8][16][68];
};

template <int MODE, bool SPLIT>
__device__ __forceinline__ void gemm_split(const float* __restrict__ Abase,
                                           const __half* __restrict__ Whi,
                                           const __half* __restrict__ Wlo,
                                           const float* __restrict__ bias,
                                           int b, int p, float* __restrict__ outp) {
    __shared__ __align__(16) SplitSmem sm;
    int s0 = blockIdx.y * 128, j0 = blockIdx.x * 128;
    int tid = threadIdx.x, lane = tid & 31, wid = tid >> 5;
    int wr = wid >> 1, wc = wid & 1;

    wmma::fragment<wmma::accumulator, 16, 16, 16, float> mainf[2][4], corrf[2][4];
#pragma unroll
    for (int i = 0; i < 2; i++)
#pragma unroll
        for (int j = 0; j < 4; j++) {
            wmma::fill_fragment(mainf[i][j], 0.f);
            if (SPLIT) wmma::fill_fragment(corrf[i][j], 0.f);
        }

    for (int kc = 0; kc < KDIM; kc += 32) {
#pragma unroll
        for (int it = 0; it < 4; it++) {
            int v = tid + it * 256;
            int r = v >> 3, c4 = (v & 7) * 4;
            int kk = kc + c4;
            const float* src;
            if (MODE == 0)
                src = Abase + (size_t)(kk >> 7) * (S * D) + (size_t)(s0 + r) * D + (kk & 127);
            else
                src = Abase + (size_t)(s0 + r) * KDIM + kk;
            float4 a = *(const float4*)src;
            __half h0 = __float2half(a.x), h1 = __float2half(a.y);
            __half h2 = __float2half(a.z), h3 = __float2half(a.w);
            sm.g.Ahi[r][c4 + 0] = h0; sm.g.Ahi[r][c4 + 1] = h1;
            sm.g.Ahi[r][c4 + 2] = h2; sm.g.Ahi[r][c4 + 3] = h3;
            if (SPLIT) {
                sm.g.Alo[r][c4 + 0] = __float2half((a.x - __half2float(h0)) * 2048.f);
                sm.g.Alo[r][c4 + 1] = __float2half((a.y - __half2float(h1)) * 2048.f);
                sm.g.Alo[r][c4 + 2] = __float2half((a.z - __half2float(h2)) * 2048.f);
                sm.g.Alo[r][c4 + 3] = __float2half((a.w - __half2float(h3)) * 2048.f);
            }
        }
#pragma unroll
        for (int it = 0; it < 2; it++) {
            int v = tid + it * 256;
            int r = v >> 4, c8 = (v & 15) * 8;
            *(uint4*)&sm.g.Bhi[r][c8] = *(const uint4*)&Whi[(size_t)(kc + r) * KDIM + j0 + c8];
            if (SPLIT)
                *(uint4*)&sm.g.Blo[r][c8] = *(const uint4*)&Wlo[(size_t)(kc + r) * KDIM + j0 + c8];
        }
        __syncthreads();
#pragma unroll
        for (int ks = 0; ks < 2; ks++) {
            int k = ks * 16;
            wmma::fragment<wmma::matrix_a, 16, 16, 16, __half, wmma::row_major> ahi[2], alo[2];
#pragma unroll
            for (int i = 0; i < 2; i++) {
                wmma::load_matrix_sync(ahi[i], &sm.g.Ahi[wr * 32 + i * 16][k], 40);
                if (SPLIT) wmma::load_matrix_sync(alo[i], &sm.g.Alo[wr * 32 + i * 16][k], 40);
            }
#pragma unroll
            for (int j = 0; j < 4; j++) {
                wmma::fragment<wmma::matrix_b, 16, 16, 16, __half, wmma::row_major> bh, bl;
                wmma::load_matrix_sync(bh, &sm.g.Bhi[k][wc * 64 + j * 16], 136);
                if (SPLIT) wmma::load_matrix_sync(bl, &sm.g.Blo[k][wc * 64 + j * 16], 136);
#pragma unroll
                for (int i = 0; i < 2; i++) {
                    wmma::mma_sync(mainf[i][j], ahi[i], bh, mainf[i][j]);
                    if (SPLIT) {
                        wmma::mma_sync(corrf[i][j], ahi[i], bl, corrf[i][j]);
                        wmma::mma_sync(corrf[i][j], alo[i], bh, corrf[i][j]);
                    }
                }
            }
        }
        __syncthreads();
    }

#pragma unroll
    for (int i = 0; i < 2; i++) {
#pragma unroll
        for (int j = 0; j < 4; j++) {
            if (SPLIT) {
#pragma unroll
                for (int e = 0; e < mainf[i][j].num_elements; e++)
                    mainf[i][j].x[e] += corrf[i][j].x[e] * (1.f / 2048.f);
            }
            wmma::store_matrix_sync(&sm.stage[wid][0][j * 16], mainf[i][j], 68,
                                    wmma::mem_row_major);
        }
        __syncwarp();
        int row = lane >> 1, colh = lane & 1;
        int s = s0 + wr * 32 + i * 16 + row;
        float sq = 0.f;
#pragma unroll
        for (int c = 0; c < 32; c++) {
            int lc = colh * 32 + c;
            int jj = j0 + wc * 64 + lc;
            float v = sm.stage[wid][row][lc] + bias[jj];
            if (MODE == 0) {
                __half h = __float2half(v);
                if (p == 0)      { g_Q16[b][s][jj] = h; sq += v * v; }
                else if (p == 1) { g_K16[b][s][jj] = h; sq += v * v; }
                else             { g_V16[b][s][jj] = h; g_Vf[b][s][jj] = v; }
            } else {
                outp[((size_t)(b * 2 + (jj >> 7)) * S + s) * H + (jj & 127)] = v;
            }
        }
        if (MODE == 0 && p < 2) {
            sq += __shfl_xor_sync(FULLMASK, sq, 1);
            if (colh == 0) {
                if (p == 0) atomicAdd(&g_q2[b][s], sq);
                else        atomicAdd(&g_k2[b][s], sq);
            }
        }
        __syncwarp();
    }
}

__global__ __launch_bounds__(256) void projQK_kernel(const float* __restrict__ Zq,
                                                     const float* __restrict__ Zk) {
    int z = blockIdx.z;
    int b = z >> 1, p = z & 1;
    const float* Zb = ((p == 0) ? Zq : Zk) + (size_t)b * 2 * S * D;
    gemm_split<0, false>(Zb, &g_Whi[p][0][0], &g_Wlo[p][0][0], g_beff[p], b, p, nullptr);
}

__global__ __launch_bounds__(256) void projV_kernel(const float* __restrict__ Zv) {
    int b = blockIdx.z;
    const float* Zb = Zv + (size_t)b * 2 * S * D;
    gemm_split<0, true>(Zb, &g_Whi[2][0][0], &g_Wlo[2][0][0], g_beff[2], b, 2, nullptr);
}

__global__ __launch_bounds__(256) void outproj_kernel(float* __restrict__ out) {
    int b = blockIdx.z;
    gemm_split<1, true>(&g_est[b][0][0], &g_Whi[3][0][0], &g_Wlo[3][0][0], g_beff[3], b, 0, out);
}

// --------------------------------------------------------------------------
// Hierarchical prefix sum of V over t (64 chunks of 64 rows) + zero g_est.
__global__ __launch_bounds__(256) void prefix1_kernel() {
    int ch = blockIdx.x, b = blockIdx.y;
    int tid = threadIdx.x;
    const float* V = &g_Vf[b][ch * 64][0];
    float s = 0.f;
#pragma unroll 8
    for (int r = 0; r < 64; r++) s += V[(size_t)r * KDIM + tid];
    g_chunk[b][ch][tid] = s;
    // zero g_est rows [ch*64, ch*64+64)
    float4 z = make_float4(0.f, 0.f, 0.f, 0.f);
    float4* E = (float4*)&g_est[b][ch * 64][0];
#pragma unroll
    for (int i = 0; i < 16; i++) E[tid + i * 256] = z;
}

__global__ __launch_bounds__(256) void prefix3_kernel() {
    int ch = blockIdx.x, b = blockIdx.y, col = threadIdx.x;
    float c = 0.f;
    for (int c2 = 0; c2 < ch; c2++) c += g_chunk[b][c2][col];
    const float* V = &g_Vf[b][ch * 64][0];
    float* C = &g_cumV[b][ch * 64][0];
#pragma unroll 4
    for (int r = 0; r < 64; r++) {
        c += V[(size_t)r * KDIM + col];
        C[(size_t)r * KDIM + col] = c;
    }
}

// --------------------------------------------------------------------------
// Logits+exp: block tile 128(M)x256(N), full K=256 resident, warp tile 64x64.
// Compute tiles (2*jN <= iT): wmma -> exp(coeff*log(...)) with causal mask +
// rowsum atomics. Other tiles: zero-fill attn.
#define LOG_ASTRIDE 264
#define LOG_AOFF 0
#define LOG_BOFF (128 * LOG_ASTRIDE * 2)            // 67584
#define LOG_SMEM (LOG_BOFF + 256 * LOG_ASTRIDE * 2) // 202752

__global__ __launch_bounds__(256) void logits_kernel(const float* __restrict__ nf_,
                                                     const float* __restrict__ tau_,
                                                     float* __restrict__ attn) {
    int jN = blockIdx.x, iT = blockIdx.y, b = blockIdx.z;
    int s0 = iT * 128, t0 = jN * 256;
    int tid = threadIdx.x, lane = tid & 31, wid = tid >> 5;

    if (2 * jN > iT) {   // entire tile above diagonal: zero-fill
        float4 z = make_float4(0.f, 0.f, 0.f, 0.f);
#pragma unroll
        for (int it = 0; it < 32; it++) {
            int f = it * 256 + tid;             // 0..8191 float4s
            int r = f >> 6, c4 = (f & 63) * 4;
            *(float4*)&attn[((size_t)(b * S + s0 + r)) * S + t0 + c4] = z;
        }
        return;
    }

    extern __shared__ __align__(16) char smem[];
    __half* Ash = (__half*)(smem + LOG_AOFF);
    __half* Bsh = (__half*)(smem + LOG_BOFF);
    uint32_t aBase = smem_u32(smem);

    // Load A (Q tile 128x256) + B (K tile 256x256) via cp.async
#pragma unroll
    for (int it = 0; it < 16; it++) {
        int v = tid + it * 256;                 // 0..4095
        int r = v >> 5, c8 = (v & 31) * 8;
        cp16(aBase + LOG_AOFF + (uint32_t)(r * LOG_ASTRIDE + c8) * 2,
             &g_Q16[b][s0 + r][c8]);
    }
#pragma unroll
    for (int it = 0; it < 32; it++) {
        int v = tid + it * 256;                 // 0..8191
        int r = v >> 5, c8 = (v & 31) * 8;
        cp16(aBase + LOG_BOFF + (uint32_t)(r * LOG_ASTRIDE + c8) * 2,
             &g_K16[b][t0 + r][c8]);
    }
    CP_COMMIT();
    CP_WAIT();
    __syncthreads();

    int wr = wid >> 2, wc = wid & 3;            // warp tile: rows wr*64, cols wc*64
    wmma::fragment<wmma::accumulator, 16, 16, 16, float> acc[4][4];
#pragma unroll
    for (int i = 0; i < 4; i++)
#pragma unroll
        for (int j = 0; j < 4; j++) wmma::fill_fragment(acc[i][j], 0.f);

#pragma unroll
    for (int ks = 0; ks < 16; ks++) {
        int k = ks * 16;
        wmma::fragment<wmma::matrix_a, 16, 16, 16, __half, wmma::row_major> a[4];
#pragma unroll
        for (int i = 0; i < 4; i++)
            wmma::load_matrix_sync(a[i], &Ash[(wr * 64 + i * 16) * LOG_ASTRIDE + k], LOG_ASTRIDE);
#pragma unroll
        for (int j = 0; j < 4; j++) {
            wmma::fragment<wmma::matrix_b, 16, 16, 16, __half, wmma::col_major> bf;
            wmma::load_matrix_sync(bf, &Bsh[(wc * 64 + j * 16) * LOG_ASTRIDE + k], LOG_ASTRIDE);
#pragma unroll
            for (int i = 0; i < 4; i++) wmma::mma_sync(acc[i][j], a[i], bf, acc[i][j]);
        }
    }

    __syncthreads();   // all warps done reading A/B before staging overwrites

    float* st = (float*)smem + wid * 64 * 68;
#pragma unroll
    for (int i = 0; i < 4; i++)
#pragma unroll
        for (int j = 0; j < 4; j++)
            wmma::store_matrix_sync(&st[(i * 16) * 68 + j * 16], acc[i][j], 68,
                                    wmma::mem_row_major);
    __syncwarp();

    float tv = tau_[0];
    float sp = (tv > 20.f) ? tv : log1pf(__expf(tv));
    float coeff = -sp * 0.08838834764831845f;   // softplus(tau)/sqrt(H)
    float nf = nf_[0];
    float nf2 = nf * nf + FEPS;

#pragma unroll
    for (int rr = 0; rr < 2; rr++) {
        int row = lane + rr * 32;               // 0..63 within warp tile
        int s = s0 + wr * 64 + row;
        float q2s = g_q2[b][s];
        size_t rowbase = ((size_t)(b * S + s)) * S;
        float esum = 0.f;
#pragma unroll
        for (int c4 = 0; c4 < 16; c4++) {
            int t = t0 + wc * 64 + c4 * 4;
            float4 re = *(float4*)&st[row * 68 + c4 * 4];
            float4 o;
            o.x = __expf(coeff * __logf(nf2 + q2s + g_k2[b][t + 0] - 2.f * re.x));
            o.y = __expf(coeff * __logf(nf2 + q2s + g_k2[b][t + 1] - 2.f * re.y));
            o.z = __expf(coeff * __logf(nf2 + q2s + g_k2[b][t + 2] - 2.f * re.z));
            o.w = __expf(coeff * __logf(nf2 + q2s + g_k2[b][t + 3] - 2.f * re.w));
            if (t + 0 > s) o.x = 0.f;
            if (t + 1 > s) o.y = 0.f;
            if (t + 2 > s) o.z = 0.f;
            if (t + 3 > s) o.w = 0.f;
            esum += (o.x + o.y) + (o.z + o.w);
            *(float4*)&attn[rowbase + t] = o;
        }
        atomicAdd(&g_rowsum[b][s], esum);
    }
}

// --------------------------------------------------------------------------
// Normalize: w = e / rowsum (streamed, in place)
__global__ __launch_bounds__(128) void normalize_kernel(float* __restrict__ attn) {
    int s = blockIdx.x, b = blockIdx.y;
    int tid = threadIdx.x;
    float inv = 1.f / g_rowsum[b][s];
    int kend = ((s >> 7) + 1) << 7;
    float* L = attn + ((size_t)(b * S + s)) * S;
    for (int i = tid * 4; i < kend; i += 512) {
        float4 e = *(float4*)&L[i];
        *(float4*)&L[i] = make_float4(e.x * inv, e.y * inv, e.z * inv, e.w * inv);
    }
}

// --------------------------------------------------------------------------
// pv: est = (dev @ V16)/1024 + cumV[s]/(s+1)
// dev built on the fly from attn: (w - 1/(s+1))*1024, causal-masked, fp16.
// Block tile 64(M) x 256(N full), warp 32x64, split-K over 2 slices,
// atomicAdd into pre-zeroed g_est (cumV term added by slice 0 only).
struct PvSmem {
    union {
        __half A[64][72];           // 9216 B
        float  stage[8][16][20];    // 10240 B
    } uA;
    __half Bm[64][264];             // 33792 B
};

__global__ __launch_bounds__(256) void pv_kernel(const float* __restrict__ attn) {
    int slice = blockIdx.x, mT = blockIdx.y, b = blockIdx.z;
    int s0 = mT * 64;
    int nchunks = mT + 1;
    int half = (nchunks + 1) >> 1;
    int c_lo = slice ? half : 0;
    int c_hi = slice ? nchunks : half;
    if (c_lo >= c_hi) return;

    __shared__ __align__(16) PvSmem sm;
    int tid = threadIdx.x, lane = tid & 31, wid = tid >> 5;
    int wr = wid >> 2, wc = wid & 3;    // warp tile: rows wr*32, cols wc*64
    uint32_t bBase = smem_u32(&sm.Bm[0][0]);

    wmma::fragment<wmma::accumulator, 16, 16, 16, float> acc[2][4];
#pragma unroll
    for (int i = 0; i < 2; i++)
#pragma unroll
        for (int j = 0; j < 4; j++) wmma::fill_fragment(acc[i][j], 0.f);

    for (int ch = c_lo; ch < c_hi; ch++) {
        int k0 = ch * 64;
        // A: 64x64 dev tile from attn (fp32 -> masked, scaled fp16)
#pragma unroll
        for (int it = 0; it < 4; it++) {
            int v = tid + it * 256;             // 0..1023
            int r = v >> 4, c4 = (v & 15) * 4;
            int s = s0 + r;
            float crow = 1.f / (float)(s + 1);
            int gcol = k0 + c4;
            float4 w4 = *(const float4*)&attn[((size_t)(b * S + s)) * S + gcol];
            float p0 = (gcol + 0 <= s) ? (w4.x - crow) * 1024.f : 0.f;
            float p1 = (gcol + 1 <= s) ? (w4.y - crow) * 1024.f : 0.f;
            float p2 = (gcol + 2 <= s) ? (w4.z - crow) * 1024.f : 0.f;
            float p3 = (gcol + 3 <= s) ? (w4.w - crow) * 1024.f : 0.f;
            *(__half2*)&sm.uA.A[r][c4]     = __floats2half2_rn(p0, p1);
            *(__half2*)&sm.uA.A[r][c4 + 2] = __floats2half2_rn(p2, p3);
        }
        // B: V16 chunk 64x256 via cp.async
#pragma unroll
        for (int it = 0; it < 8; it++) {
            int v = tid + it * 256;             // 0..2047
            int r = v >> 5, c8 = (v & 31) * 8;
            cp16(bBase + (uint32_t)(r * 264 + c8) * 2, &g_V16[b][k0 + r][c8]);
        }
        CP_COMMIT();
        CP_WAIT();
        __syncthreads();
#pragma unroll
        for (int ks = 0; ks < 4; ks++) {
            int k = ks * 16;
            wmma::fragment<wmma::matrix_a, 16, 16, 16, __half, wmma::row_major> a[2];
#pragma unroll
            for (int i = 0; i < 2; i++)
                wmma::load_matrix_sync(a[i], &sm.uA.A[wr * 32 + i * 16][k], 72);
#pragma unroll
            for (int j = 0; j < 4; j++) {
                wmma::fragment<wmma::matrix_b, 16, 16, 16, __half, wmma::row_major> bf;
                wmma::load_matrix_sync(bf, &sm.Bm[k][wc * 64 + j * 16], 264);
#pragma unroll
                for (int i = 0; i < 2; i++) wmma::mma_sync(acc[i][j], a[i], bf, acc[i][j]);
            }
        }
        __syncthreads();
    }

    // epilogue: per-fragment staging, atomicAdd into g_est
#pragma unroll
    for (int i = 0; i < 2; i++) {
#pragma unroll
        for (int j = 0; j < 4; j++) {
            wmma::store_matrix_sync(&sm.uA.stage[wid][0][0], acc[i][j], 20,
                                    wmma::mem_row_major);
            __syncwarp();
            int row = lane >> 1, colh = lane & 1;
            int s = s0 + wr * 32 + i * 16 + row;
            float invn = 1.f / (float)(s + 1);
            int nb = wc * 64 + j * 16 + colh * 8;
#pragma unroll
            for (int c = 0; c < 8; c++) {
                int col = nb + c;
                float v = sm.uA.stage[wid][row][colh * 8 + c] * (1.f / 1024.f);
                if (slice == 0) v += g_cumV[b][s][col] * invn;
                atomicAdd(&g_est[b][s][col], v);
            }
            __syncwarp();
        }
    }
}

// --------------------------------------------------------------------------
extern "C" void kernel_launch(void* const* d_in, const int* in_sizes, int n_in,
                              void* d_out, int out_size) {
    (void)in_sizes; (void)n_in; (void)out_size;
    const float* Zq  = (const float*)d_in[0];
    const float* Zk  = (const float*)d_in[1];
    const float* Zv  = (const float*)d_in[2];
    const float* nf  = (const float*)d_in[19];
    const float* tau = (const float*)d_in[20];
    float* out  = (float*)d_out;                    // (B,2,S,H,1)
    float* attn = out + (size_t)BATCH * 2 * S * H;  // (B,S,S)

    cudaFuncSetAttribute(logits_kernel, cudaFuncAttributeMaxDynamicSharedMemorySize,
                         LOG_SMEM);

    pack_all_kernel<<<dim3(256, 4), 256>>>(
        (const float*)d_in[3],  (const float*)d_in[4],  (const float*)d_in[5],  (const float*)d_in[6],
        (const float*)d_in[7],  (const float*)d_in[8],  (const float*)d_in[9],  (const float*)d_in[10],
        (const float*)d_in[11], (const float*)d_in[12], (const float*)d_in[13], (const float*)d_in[14],
        (const float*)d_in[15], (const float*)d_in[16], (const float*)d_in[17], (const float*)d_in[18]);

    projQK_kernel<<<dim3(2, 32, 4), 256>>>(Zq, Zk);
    projV_kernel<<<dim3(2, 32, BATCH), 256>>>(Zv);
    prefix1_kernel<<<dim3(64, BATCH), 256>>>();
    prefix3_kernel<<<dim3(64, BATCH), 256>>>();
    logits_kernel<<<dim3(16, 32, BATCH), 256, LOG_SMEM>>>(nf, tau, attn);
    normalize_kernel<<<dim3(S, BATCH), 128>>>(attn);
    pv_kernel<<<dim3(2, 64, BATCH), 256>>>(attn);
    outproj_kernel<<<dim3(2, 32, BATCH), 256>>>(out);
}